// round 15
// baseline (speedup 1.0000x reference)
#include <cuda_runtime.h>
#include <cstdint>

#define N_NODES 100000
#define N_EDGES 1600000
#define BN_EPS  1e-5f
#define CAP     64          // padded-CSR bucket capacity (max in-degree ~40)
#define CAPSH   6
#define NBANK   8           // replicated BN-stat banks

// ---------------- scratch (static __device__, no allocations) ----------------
__device__ int    g_count[N_NODES];         // in-degree, built by scatter
__device__ int    g_col[N_NODES * CAP];     // padded CSR: sources per dst
__device__ float  g_dinv[N_NODES];
__device__ float4 g_b0[N_NODES * 12];       // rows: L1 in (20f) / p2 (48f) / p3 (32f)
__device__ float4 g_b1[N_NODES * 12];       // agg2 (48f)
__device__ float4 g_b2[N_NODES * 16];       // h1 (64f) / agg3 (32f)
__device__ float  g_bnpart[3][NBANK][128];  // banked stats: [f]=sum, [64+f]=sumsq

template<int B> __device__ __forceinline__ float4* buf4() {
    if (B == 0) return g_b0;
    if (B == 1) return g_b1;
    return g_b2;
}
template<int B> __device__ __forceinline__ float* buff() {
    return (float*)buf4<B>();
}

// ------- padded-CSR scatter: pos = old count; col[dst*CAP+pos] = src --------
__global__ void k_scatter(const int* __restrict__ ei) {
    int t = blockIdx.x * blockDim.x + threadIdx.x;
    if (t < N_EDGES / 4) {
        int4 s4 = reinterpret_cast<const int4*>(ei)[t];
        int4 d4 = reinterpret_cast<const int4*>(ei + N_EDGES)[t];
        int p0 = atomicAdd(&g_count[d4.x], 1);
        if (p0 < CAP) g_col[(d4.x << CAPSH) + p0] = s4.x;
        int p1 = atomicAdd(&g_count[d4.y], 1);
        if (p1 < CAP) g_col[(d4.y << CAPSH) + p1] = s4.y;
        int p2 = atomicAdd(&g_count[d4.z], 1);
        if (p2 < CAP) g_col[(d4.z << CAPSH) + p2] = s4.z;
        int p3 = atomicAdd(&g_count[d4.w], 1);
        if (p3 < CAP) g_col[(d4.w << CAPSH) + p3] = s4.w;
    }
}

// ------- prep: dinv = rsqrt(deg+1); b0 rows (20 floats) = dinv .* x ---------
__global__ void k_prep(const float* __restrict__ x) {
    int i = blockIdx.x * blockDim.x + threadIdx.x;
    if (i < N_NODES) {
        float d = rsqrtf((float)g_count[i] + 1.0f);
        g_dinv[i] = d;
        const float4* xr = reinterpret_cast<const float4*>(x) + i * 5;
        float4* row = g_b0 + i * 5;
        #pragma unroll
        for (int c = 0; c < 5; c++) {
            float4 v = xr[c];
            v.x *= d; v.y *= d; v.z *= d; v.w *= d;
            row[c] = v;
        }
    }
}

// ------- fused layer 1: gather(20f) + GEMM 20->64 (reg weights) + BN1 stats --
__global__ void k_layer1(const float* __restrict__ W1) {
    const int tid = threadIdx.x, lane = tid & 31;
    float w_lo[20], w_hi[20];
    #pragma unroll
    for (int k = 0; k < 20; k++) {
        w_lo[k] = W1[k * 64 + lane];
        w_hi[k] = W1[k * 64 + 32 + lane];
    }
    __shared__ float bsum[64];
    __shared__ float bsq[64];
    for (int i = tid; i < 64; i += blockDim.x) { bsum[i] = 0.f; bsq[i] = 0.f; }
    __syncthreads();
    const int grp = lane / 5;          // 0..6 (grp 6 = lanes 30,31 inactive)
    const int c   = lane % 5;
    const bool active = grp < 6;
    const float4* __restrict__ p4 = g_b0;
    float* __restrict__ h = (float*)g_b2;
    int warp = (blockIdx.x * blockDim.x + tid) >> 5;
    const int nwarps = (gridDim.x * blockDim.x) >> 5;
    float s_lo = 0.f, q_lo = 0.f, s_hi = 0.f, q_hi = 0.f;
    for (int i0 = warp * 2; i0 < N_NODES; i0 += nwarps * 2) {
        const int i1 = i0 + 1;                   // N_NODES even
        const int cntA = min(g_count[i0], CAP);
        const int cntB = min(g_count[i1], CAP);
        const int begA = i0 << CAPSH, begB = i1 << CAPSH;
        float4 accA = {0.f, 0.f, 0.f, 0.f}, accB = {0.f, 0.f, 0.f, 0.f};
        if (grp == 0) { accA = p4[i0 * 5 + c]; accB = p4[i1 * 5 + c]; }
        const int mx = max(cntA, cntB);
        for (int j = grp; j < mx; j += 6) {
            if (active && j < cntA) {
                int idx = g_col[begA + j];
                float4 v = p4[idx * 5 + c];
                accA.x += v.x; accA.y += v.y; accA.z += v.z; accA.w += v.w;
            }
            if (active && j < cntB) {
                int idx = g_col[begB + j];
                float4 v = p4[idx * 5 + c];
                accB.x += v.x; accB.y += v.y; accB.z += v.z; accB.w += v.w;
            }
        }
        // guarded reduction: slots at lanes 0,5,10,15,20,25
        #pragma unroll
        for (int d = 5; d <= 20; d <<= 1) {     // d = 5, 10, 20
            float tax = __shfl_down_sync(0xffffffffu, accA.x, d);
            float tay = __shfl_down_sync(0xffffffffu, accA.y, d);
            float taz = __shfl_down_sync(0xffffffffu, accA.z, d);
            float taw = __shfl_down_sync(0xffffffffu, accA.w, d);
            float tbx = __shfl_down_sync(0xffffffffu, accB.x, d);
            float tby = __shfl_down_sync(0xffffffffu, accB.y, d);
            float tbz = __shfl_down_sync(0xffffffffu, accB.z, d);
            float tbw = __shfl_down_sync(0xffffffffu, accB.w, d);
            if (lane + d < 32) {
                accA.x += tax; accA.y += tay; accA.z += taz; accA.w += taw;
                accB.x += tbx; accB.y += tby; accB.z += tbz; accB.w += tbw;
            }
        }
        float oA0 = 0.f, oA1 = 0.f, oB0 = 0.f, oB1 = 0.f;
        #pragma unroll
        for (int k4 = 0; k4 < 5; k4++) {
            float ax = __shfl_sync(0xffffffffu, accA.x, k4);
            float ay = __shfl_sync(0xffffffffu, accA.y, k4);
            float az = __shfl_sync(0xffffffffu, accA.z, k4);
            float aw = __shfl_sync(0xffffffffu, accA.w, k4);
            float bx = __shfl_sync(0xffffffffu, accB.x, k4);
            float by = __shfl_sync(0xffffffffu, accB.y, k4);
            float bz = __shfl_sync(0xffffffffu, accB.z, k4);
            float bw = __shfl_sync(0xffffffffu, accB.w, k4);
            int k = k4 * 4;
            oA0 = fmaf(ax, w_lo[k],     oA0); oA1 = fmaf(ax, w_hi[k],     oA1);
            oA0 = fmaf(ay, w_lo[k + 1], oA0); oA1 = fmaf(ay, w_hi[k + 1], oA1);
            oA0 = fmaf(az, w_lo[k + 2], oA0); oA1 = fmaf(az, w_hi[k + 2], oA1);
            oA0 = fmaf(aw, w_lo[k + 3], oA0); oA1 = fmaf(aw, w_hi[k + 3], oA1);
            oB0 = fmaf(bx, w_lo[k],     oB0); oB1 = fmaf(bx, w_hi[k],     oB1);
            oB0 = fmaf(by, w_lo[k + 1], oB0); oB1 = fmaf(by, w_hi[k + 1], oB1);
            oB0 = fmaf(bz, w_lo[k + 2], oB0); oB1 = fmaf(bz, w_hi[k + 2], oB1);
            oB0 = fmaf(bw, w_lo[k + 3], oB0); oB1 = fmaf(bw, w_hi[k + 3], oB1);
        }
        float dA = g_dinv[i0], dB = g_dinv[i1];
        oA0 *= dA; oA1 *= dA; oB0 *= dB; oB1 *= dB;
        h[i0 * 64 + lane]      = oA0;
        h[i0 * 64 + 32 + lane] = oA1;
        h[i1 * 64 + lane]      = oB0;
        h[i1 * 64 + 32 + lane] = oB1;
        s_lo += oA0 + oB0; q_lo += oA0 * oA0 + oB0 * oB0;
        s_hi += oA1 + oB1; q_hi += oA1 * oA1 + oB1 * oB1;
    }
    atomicAdd(&bsum[lane], s_lo);      atomicAdd(&bsq[lane], q_lo);
    atomicAdd(&bsum[32 + lane], s_hi); atomicAdd(&bsq[32 + lane], q_hi);
    __syncthreads();
    float* bank = g_bnpart[0][blockIdx.x & (NBANK - 1)];
    for (int i = tid; i < 64; i += blockDim.x) {
        atomicAdd(&bank[i],      bsum[i]);
        atomicAdd(&bank[64 + i], bsq[i]);
    }
}

// ------- dual-node gather-aggregate: out[i]=dinv[i]*(self+sum p[src]) -------
template<int FPAD, int EPW, int PB, int OB, int STATS>
__global__ void k_gather() {
    constexpr int LW = FPAD / 4;
    constexpr bool ST = (STATS >= 0);
    constexpr int LIDX = ST ? STATS : 0;
    const float4* __restrict__ p4 = buf4<PB>();
    float4* __restrict__ o4 = buf4<OB>();
    __shared__ float bsum[ST ? FPAD : 1];
    __shared__ float bsq[ST ? FPAD : 1];
    const int tid = threadIdx.x;
    const int lane = tid & 31;
    const int grp = lane / LW;
    const int c   = lane % LW;
    const bool active = grp < EPW;
    if (ST) {
        for (int i = tid; i < FPAD; i += blockDim.x) { bsum[i] = 0.f; bsq[i] = 0.f; }
        __syncthreads();
    }
    int warp = (blockIdx.x * blockDim.x + tid) >> 5;
    const int nwarps = (gridDim.x * blockDim.x) >> 5;
    float4 s4 = {0.f, 0.f, 0.f, 0.f}, q4 = {0.f, 0.f, 0.f, 0.f};
    for (int i0 = warp * 2; i0 < N_NODES; i0 += nwarps * 2) {
        const int i1 = i0 + 1;
        const int cntA = min(g_count[i0], CAP);
        const int cntB = min(g_count[i1], CAP);
        const int begA = i0 << CAPSH, begB = i1 << CAPSH;
        float4 accA = {0.f, 0.f, 0.f, 0.f}, accB = {0.f, 0.f, 0.f, 0.f};
        if (grp == 0) { accA = p4[i0 * LW + c]; accB = p4[i1 * LW + c]; }
        const int mx = max(cntA, cntB);
        for (int j = grp; j < mx; j += EPW) {
            if (active && j < cntA) {
                int idx = g_col[begA + j];
                float4 v = p4[idx * LW + c];
                accA.x += v.x; accA.y += v.y; accA.z += v.z; accA.w += v.w;
            }
            if (active && j < cntB) {
                int idx = g_col[begB + j];
                float4 v = p4[idx * LW + c];
                accB.x += v.x; accB.y += v.y; accB.z += v.z; accB.w += v.w;
            }
        }
        if (LW == 8) {
            #pragma unroll
            for (int off = 8; off < 32; off <<= 1) {
                accA.x += __shfl_xor_sync(0xffffffffu, accA.x, off);
                accA.y += __shfl_xor_sync(0xffffffffu, accA.y, off);
                accA.z += __shfl_xor_sync(0xffffffffu, accA.z, off);
                accA.w += __shfl_xor_sync(0xffffffffu, accA.w, off);
                accB.x += __shfl_xor_sync(0xffffffffu, accB.x, off);
                accB.y += __shfl_xor_sync(0xffffffffu, accB.y, off);
                accB.z += __shfl_xor_sync(0xffffffffu, accB.z, off);
                accB.w += __shfl_xor_sync(0xffffffffu, accB.w, off);
            }
        } else {                        // LW == 12, EPW == 2: slot1 -> slot0
            accA.x += __shfl_down_sync(0xffffffffu, accA.x, 12);
            accA.y += __shfl_down_sync(0xffffffffu, accA.y, 12);
            accA.z += __shfl_down_sync(0xffffffffu, accA.z, 12);
            accA.w += __shfl_down_sync(0xffffffffu, accA.w, 12);
            accB.x += __shfl_down_sync(0xffffffffu, accB.x, 12);
            accB.y += __shfl_down_sync(0xffffffffu, accB.y, 12);
            accB.z += __shfl_down_sync(0xffffffffu, accB.z, 12);
            accB.w += __shfl_down_sync(0xffffffffu, accB.w, 12);
        }
        if (grp == 0) {
            float dA = g_dinv[i0], dB = g_dinv[i1];
            float4 oA = {dA * accA.x, dA * accA.y, dA * accA.z, dA * accA.w};
            float4 oB = {dB * accB.x, dB * accB.y, dB * accB.z, dB * accB.w};
            o4[i0 * LW + c] = oA;
            o4[i1 * LW + c] = oB;
            if (ST) {
                s4.x += oA.x + oB.x; s4.y += oA.y + oB.y;
                s4.z += oA.z + oB.z; s4.w += oA.w + oB.w;
                q4.x += oA.x * oA.x + oB.x * oB.x;
                q4.y += oA.y * oA.y + oB.y * oB.y;
                q4.z += oA.z * oA.z + oB.z * oB.z;
                q4.w += oA.w * oA.w + oB.w * oB.w;
            }
        }
    }
    if (ST) {
        if (grp == 0) {
            atomicAdd(&bsum[c * 4 + 0], s4.x); atomicAdd(&bsq[c * 4 + 0], q4.x);
            atomicAdd(&bsum[c * 4 + 1], s4.y); atomicAdd(&bsq[c * 4 + 1], q4.y);
            atomicAdd(&bsum[c * 4 + 2], s4.z); atomicAdd(&bsq[c * 4 + 2], q4.z);
            atomicAdd(&bsum[c * 4 + 3], s4.w); atomicAdd(&bsq[c * 4 + 3], q4.w);
        }
        __syncthreads();
        float* bank = g_bnpart[LIDX][blockIdx.x & (NBANK - 1)];
        for (int i = tid; i < FPAD; i += blockDim.x) {
            atomicAdd(&bank[i],      bsum[i]);
            atomicAdd(&bank[64 + i], bsq[i]);
        }
    }
}

// ------ register-tiled GEMM, NT=2 fine tiles, inline BN-param ---------------
template<int FIN, int IS, int FOUT, int NC, int NG, int NT,
         int BNL, bool DINV_OUT, int IB, int OB>
__global__ void k_gemm(const float* __restrict__ W,
                       const float* __restrict__ gv,
                       const float* __restrict__ bev) {
    constexpr int NO   = 4;
    constexpr int NPB  = NG * NT;
    constexpr int SPAD = FIN + 4;
    constexpr bool BN_IN = (BNL >= 0);
    constexpr int BL = BN_IN ? BNL : 0;
    const float* __restrict__ in = buff<IB>();
    float* __restrict__ out = buff<OB>();
    __shared__ float sW[FIN * FOUT];
    __shared__ float sIn[NPB * SPAD];
    __shared__ float sbna[BN_IN ? FIN : 1];
    __shared__ float sbnc[BN_IN ? FIN : 1];
    const int tid = threadIdx.x;
    const int nthreads = NC * NG;
    for (int idx = tid; idx < FIN * FOUT / 4; idx += nthreads)
        reinterpret_cast<float4*>(sW)[idx] = reinterpret_cast<const float4*>(W)[idx];
    if (BN_IN && tid < FIN) {
        float sum = 0.f, sq = 0.f;
        #pragma unroll
        for (int b = 0; b < NBANK; b++) {
            sum += g_bnpart[BL][b][tid];
            sq  += g_bnpart[BL][b][64 + tid];
        }
        float inv_n = 1.0f / (float)N_NODES;
        float mu  = sum * inv_n;
        float var = sq * inv_n - mu * mu;
        float a = gv[tid] * rsqrtf(var + BN_EPS);
        sbna[tid] = a;
        sbnc[tid] = bev[tid] - mu * a;
    }
    const int co = tid % NC;
    const int g  = tid / NC;
    const int base = blockIdx.x * NPB;      // one tile per block
    __syncthreads();
    for (int idx = tid; idx < NPB * (FIN / 4); idx += nthreads) {
        int nl = idx / (FIN / 4), k4 = idx - nl * (FIN / 4);
        int node = base + nl;
        float4 v = {0.f, 0.f, 0.f, 0.f};
        if (node < N_NODES) {
            v = *reinterpret_cast<const float4*>(&in[node * IS + k4 * 4]);
            if (BN_IN) {
                int k = k4 * 4;
                v.x = fmaxf(fmaf(v.x, sbna[k],     sbnc[k]),     0.f);
                v.y = fmaxf(fmaf(v.y, sbna[k + 1], sbnc[k + 1]), 0.f);
                v.z = fmaxf(fmaf(v.z, sbna[k + 2], sbnc[k + 2]), 0.f);
                v.w = fmaxf(fmaf(v.w, sbna[k + 3], sbnc[k + 3]), 0.f);
            }
        }
        *reinterpret_cast<float4*>(&sIn[nl * SPAD + k4 * 4]) = v;
    }
    __syncthreads();
    float acc[NT][NO];
    #pragma unroll
    for (int j = 0; j < NT; j++)
        #pragma unroll
        for (int o = 0; o < NO; o++) acc[j][o] = 0.f;
    #pragma unroll 2
    for (int k4 = 0; k4 < FIN / 4; k4++) {
        float4 a[NT];
        #pragma unroll
        for (int j = 0; j < NT; j++)
            a[j] = *reinterpret_cast<const float4*>(
                &sIn[(g * NT + j) * SPAD + k4 * 4]);
        #pragma unroll
        for (int kk = 0; kk < 4; kk++) {
            float4 w = *reinterpret_cast<const float4*>(
                &sW[(k4 * 4 + kk) * FOUT + co * NO]);
            #pragma unroll
            for (int j = 0; j < NT; j++) {
                float av = (kk == 0) ? a[j].x : (kk == 1) ? a[j].y
                         : (kk == 2) ? a[j].z : a[j].w;
                acc[j][0] = fmaf(av, w.x, acc[j][0]);
                acc[j][1] = fmaf(av, w.y, acc[j][1]);
                acc[j][2] = fmaf(av, w.z, acc[j][2]);
                acc[j][3] = fmaf(av, w.w, acc[j][3]);
            }
        }
    }
    #pragma unroll
    for (int j = 0; j < NT; j++) {
        int node = base + g * NT + j;
        if (node < N_NODES) {
            float d = DINV_OUT ? g_dinv[node] : 1.f;
            float4 o = {acc[j][0] * d, acc[j][1] * d, acc[j][2] * d, acc[j][3] * d};
            *reinterpret_cast<float4*>(&out[node * FOUT + co * NO]) = o;
        }
    }
}

// ------- final apply: out = bn3(b2 rows, stride 32), params inline ----------
__global__ void k_apply(const float* __restrict__ gv,
                        const float* __restrict__ bev,
                        float* __restrict__ out) {
    __shared__ float sa[32];
    __shared__ float sc[32];
    const int tid = threadIdx.x;
    if (tid < 32) {
        float sum = 0.f, sq = 0.f;
        #pragma unroll
        for (int b = 0; b < NBANK; b++) {
            sum += g_bnpart[2][b][tid];
            sq  += g_bnpart[2][b][64 + tid];
        }
        float inv_n = 1.0f / (float)N_NODES;
        float mu  = sum * inv_n;
        float var = sq * inv_n - mu * mu;
        float a = gv[tid] * rsqrtf(var + BN_EPS);
        sa[tid] = a;
        sc[tid] = bev[tid] - mu * a;
    }
    __syncthreads();
    const int total = N_NODES * 32;
    const int stride = gridDim.x * blockDim.x;
    for (int idx = blockIdx.x * blockDim.x + tid; idx < total; idx += stride) {
        int f = idx & 31;
        out[idx] = fmaf(((const float*)g_b2)[idx], sa[f], sc[f]);
    }
}

// ---------------- launcher ----------------
extern "C" void kernel_launch(void* const* d_in, const int* in_sizes, int n_in,
                              void* d_out, int out_size) {
    const float* x   = (const float*)d_in[0];
    const int*   ei  = (const int*)d_in[1];          // int32
    const float* W1  = (const float*)d_in[2];
    const float* g1  = (const float*)d_in[4];
    const float* be1 = (const float*)d_in[5];
    const float* W2  = (const float*)d_in[6];
    const float* g2  = (const float*)d_in[8];
    const float* be2 = (const float*)d_in[9];
    const float* W3  = (const float*)d_in[10];
    const float* g3  = (const float*)d_in[12];
    const float* be3 = (const float*)d_in[13];
    float* out = (float*)d_out;

    // zero per-call state (memset nodes, not kernel launches)
    void* pa;
    cudaGetSymbolAddress(&pa, g_count);
    cudaMemsetAsync(pa, 0, sizeof(int) * N_NODES);
    cudaGetSymbolAddress(&pa, g_bnpart);
    cudaMemsetAsync(pa, 0, sizeof(float) * 3 * NBANK * 128);

    // ---- build + prep ----
    k_scatter<<<(N_EDGES / 4 + 255) / 256, 256>>>(ei);        // 0
    k_prep<<<(N_NODES + 255) / 256, 256>>>(x);                // 1

    // ---- layer 1 fused: gather(20f) + GEMM 20->64 + BN1 stats ----
    k_layer1<<<2048, 256>>>(W1);                              // 2: b0 -> b2

    // ---- layer 2 ----  NT=2, NPB=40, one tile/block (2500 blocks)
    k_gemm<64, 64, 48, 12, 20, 2, 0, true, 2, 0>
        <<<(N_NODES + 39) / 40, 240>>>(W2, g1, be1);          // 3 <- PROFILED: b2 -> b0
    k_gather<48, 2, 0, 1, 1><<<2048, 256>>>();                // 4: b0 -> b1 (+BN2 stats)

    // ---- layer 3 ----  NT=2, NPB=64, one tile/block (1563 blocks)
    k_gemm<48, 48, 32, 8, 32, 2, 1, true, 1, 0>
        <<<(N_NODES + 63) / 64, 256>>>(W3, g2, be2);          // 5: b1 -> b0
    k_gather<32, 4, 0, 2, 2><<<2048, 256>>>();                // 6: b0 -> b2 (+BN3 stats)

    // ---- final BN apply (params inline) ----
    k_apply<<<2048, 256>>>(g3, be3, out);                     // 7
}

// round 16
// speedup vs baseline: 1.0710x; 1.0710x over previous
#include <cuda_runtime.h>
#include <cstdint>

#define N_NODES 100000
#define N_EDGES 1600000
#define BN_EPS  1e-5f
#define CAP     64          // padded-CSR bucket capacity (max in-degree ~40)
#define CAPSH   6
#define NBANK   8           // replicated BN-stat banks

// ---------------- scratch (static __device__, no allocations) ----------------
__device__ int    g_count[N_NODES];         // in-degree, built by scatter
__device__ int    g_col[N_NODES * CAP];     // padded CSR: sources per dst
__device__ float  g_dinv[N_NODES];
__device__ float4 g_b0[N_NODES * 12];       // rows: L1 in (20f) / p2 (48f) / p3 (32f)
__device__ float4 g_b1[N_NODES * 12];       // agg2 (48f)
__device__ float4 g_b2[N_NODES * 16];       // h1 (64f) / agg3 (32f)
__device__ float  g_bnpart[3][NBANK][128];  // banked stats: [f]=sum, [64+f]=sumsq

template<int B> __device__ __forceinline__ float4* buf4() {
    if (B == 0) return g_b0;
    if (B == 1) return g_b1;
    return g_b2;
}
template<int B> __device__ __forceinline__ float* buff() {
    return (float*)buf4<B>();
}

// ------- padded-CSR scatter: pos = old count; col[dst*CAP+pos] = src --------
__global__ void k_scatter(const int* __restrict__ ei) {
    int t = blockIdx.x * blockDim.x + threadIdx.x;
    if (t < N_EDGES / 2) {
        int2 s2 = reinterpret_cast<const int2*>(ei)[t];
        int2 d2 = reinterpret_cast<const int2*>(ei + N_EDGES)[t];
        int p0 = atomicAdd(&g_count[d2.x], 1);
        if (p0 < CAP) g_col[(d2.x << CAPSH) + p0] = s2.x;
        int p1 = atomicAdd(&g_count[d2.y], 1);
        if (p1 < CAP) g_col[(d2.y << CAPSH) + p1] = s2.y;
    }
}

// ------- prep: dinv = rsqrt(deg+1); b0 rows (20 floats) = dinv .* x ---------
__global__ void k_prep(const float* __restrict__ x) {
    int i = blockIdx.x * blockDim.x + threadIdx.x;
    if (i < N_NODES) {
        float d = rsqrtf((float)g_count[i] + 1.0f);
        g_dinv[i] = d;
        const float4* xr = reinterpret_cast<const float4*>(x) + i * 5;
        float4* row = g_b0 + i * 5;
        #pragma unroll
        for (int c = 0; c < 5; c++) {
            float4 v = xr[c];
            v.x *= d; v.y *= d; v.z *= d; v.w *= d;
            row[c] = v;
        }
    }
}

// ------- fused layer 1: gather(20f) + GEMM 20->64 (reg weights) + BN1 stats --
__global__ void k_layer1(const float* __restrict__ W1) {
    const int tid = threadIdx.x, lane = tid & 31;
    float w_lo[20], w_hi[20];
    #pragma unroll
    for (int k = 0; k < 20; k++) {
        w_lo[k] = W1[k * 64 + lane];
        w_hi[k] = W1[k * 64 + 32 + lane];
    }
    __shared__ float bsum[64];
    __shared__ float bsq[64];
    for (int i = tid; i < 64; i += blockDim.x) { bsum[i] = 0.f; bsq[i] = 0.f; }
    __syncthreads();
    const int grp = lane / 5;          // 0..6 (grp 6 = lanes 30,31 inactive)
    const int c   = lane % 5;
    const bool active = grp < 6;
    const float4* __restrict__ p4 = g_b0;
    float* __restrict__ h = (float*)g_b2;
    int warp = (blockIdx.x * blockDim.x + tid) >> 5;
    const int nwarps = (gridDim.x * blockDim.x) >> 5;
    float s_lo = 0.f, q_lo = 0.f, s_hi = 0.f, q_hi = 0.f;
    for (int i0 = warp * 2; i0 < N_NODES; i0 += nwarps * 2) {
        const int i1 = i0 + 1;                   // N_NODES even
        const int cntA = min(g_count[i0], CAP);
        const int cntB = min(g_count[i1], CAP);
        const int begA = i0 << CAPSH, begB = i1 << CAPSH;
        float4 accA = {0.f, 0.f, 0.f, 0.f}, accB = {0.f, 0.f, 0.f, 0.f};
        if (grp == 0) { accA = p4[i0 * 5 + c]; accB = p4[i1 * 5 + c]; }
        const int mx = max(cntA, cntB);
        for (int j = grp; j < mx; j += 6) {
            if (active && j < cntA) {
                int idx = g_col[begA + j];
                float4 v = p4[idx * 5 + c];
                accA.x += v.x; accA.y += v.y; accA.z += v.z; accA.w += v.w;
            }
            if (active && j < cntB) {
                int idx = g_col[begB + j];
                float4 v = p4[idx * 5 + c];
                accB.x += v.x; accB.y += v.y; accB.z += v.z; accB.w += v.w;
            }
        }
        // guarded reduction: slots at lanes 0,5,10,15,20,25
        #pragma unroll
        for (int d = 5; d <= 20; d <<= 1) {     // d = 5, 10, 20
            float tax = __shfl_down_sync(0xffffffffu, accA.x, d);
            float tay = __shfl_down_sync(0xffffffffu, accA.y, d);
            float taz = __shfl_down_sync(0xffffffffu, accA.z, d);
            float taw = __shfl_down_sync(0xffffffffu, accA.w, d);
            float tbx = __shfl_down_sync(0xffffffffu, accB.x, d);
            float tby = __shfl_down_sync(0xffffffffu, accB.y, d);
            float tbz = __shfl_down_sync(0xffffffffu, accB.z, d);
            float tbw = __shfl_down_sync(0xffffffffu, accB.w, d);
            if (lane + d < 32) {
                accA.x += tax; accA.y += tay; accA.z += taz; accA.w += taw;
                accB.x += tbx; accB.y += tby; accB.z += tbz; accB.w += tbw;
            }
        }
        float oA0 = 0.f, oA1 = 0.f, oB0 = 0.f, oB1 = 0.f;
        #pragma unroll
        for (int k4 = 0; k4 < 5; k4++) {
            float ax = __shfl_sync(0xffffffffu, accA.x, k4);
            float ay = __shfl_sync(0xffffffffu, accA.y, k4);
            float az = __shfl_sync(0xffffffffu, accA.z, k4);
            float aw = __shfl_sync(0xffffffffu, accA.w, k4);
            float bx = __shfl_sync(0xffffffffu, accB.x, k4);
            float by = __shfl_sync(0xffffffffu, accB.y, k4);
            float bz = __shfl_sync(0xffffffffu, accB.z, k4);
            float bw = __shfl_sync(0xffffffffu, accB.w, k4);
            int k = k4 * 4;
            oA0 = fmaf(ax, w_lo[k],     oA0); oA1 = fmaf(ax, w_hi[k],     oA1);
            oA0 = fmaf(ay, w_lo[k + 1], oA0); oA1 = fmaf(ay, w_hi[k + 1], oA1);
            oA0 = fmaf(az, w_lo[k + 2], oA0); oA1 = fmaf(az, w_hi[k + 2], oA1);
            oA0 = fmaf(aw, w_lo[k + 3], oA0); oA1 = fmaf(aw, w_hi[k + 3], oA1);
            oB0 = fmaf(bx, w_lo[k],     oB0); oB1 = fmaf(bx, w_hi[k],     oB1);
            oB0 = fmaf(by, w_lo[k + 1], oB0); oB1 = fmaf(by, w_hi[k + 1], oB1);
            oB0 = fmaf(bz, w_lo[k + 2], oB0); oB1 = fmaf(bz, w_hi[k + 2], oB1);
            oB0 = fmaf(bw, w_lo[k + 3], oB0); oB1 = fmaf(bw, w_hi[k + 3], oB1);
        }
        float dA = g_dinv[i0], dB = g_dinv[i1];
        oA0 *= dA; oA1 *= dA; oB0 *= dB; oB1 *= dB;
        h[i0 * 64 + lane]      = oA0;
        h[i0 * 64 + 32 + lane] = oA1;
        h[i1 * 64 + lane]      = oB0;
        h[i1 * 64 + 32 + lane] = oB1;
        s_lo += oA0 + oB0; q_lo += oA0 * oA0 + oB0 * oB0;
        s_hi += oA1 + oB1; q_hi += oA1 * oA1 + oB1 * oB1;
    }
    atomicAdd(&bsum[lane], s_lo);      atomicAdd(&bsq[lane], q_lo);
    atomicAdd(&bsum[32 + lane], s_hi); atomicAdd(&bsq[32 + lane], q_hi);
    __syncthreads();
    float* bank = g_bnpart[0][blockIdx.x & (NBANK - 1)];
    for (int i = tid; i < 64; i += blockDim.x) {
        atomicAdd(&bank[i],      bsum[i]);
        atomicAdd(&bank[64 + i], bsq[i]);
    }
}

// ------- dual-node gather-aggregate: out[i]=dinv[i]*(self+sum p[src]) -------
template<int FPAD, int EPW, int PB, int OB, int STATS>
__global__ void k_gather() {
    constexpr int LW = FPAD / 4;
    constexpr bool ST = (STATS >= 0);
    constexpr int LIDX = ST ? STATS : 0;
    const float4* __restrict__ p4 = buf4<PB>();
    float4* __restrict__ o4 = buf4<OB>();
    __shared__ float bsum[ST ? FPAD : 1];
    __shared__ float bsq[ST ? FPAD : 1];
    const int tid = threadIdx.x;
    const int lane = tid & 31;
    const int grp = lane / LW;
    const int c   = lane % LW;
    const bool active = grp < EPW;
    if (ST) {
        for (int i = tid; i < FPAD; i += blockDim.x) { bsum[i] = 0.f; bsq[i] = 0.f; }
        __syncthreads();
    }
    int warp = (blockIdx.x * blockDim.x + tid) >> 5;
    const int nwarps = (gridDim.x * blockDim.x) >> 5;
    float4 s4 = {0.f, 0.f, 0.f, 0.f}, q4 = {0.f, 0.f, 0.f, 0.f};
    for (int i0 = warp * 2; i0 < N_NODES; i0 += nwarps * 2) {
        const int i1 = i0 + 1;
        const int cntA = min(g_count[i0], CAP);
        const int cntB = min(g_count[i1], CAP);
        const int begA = i0 << CAPSH, begB = i1 << CAPSH;
        float4 accA = {0.f, 0.f, 0.f, 0.f}, accB = {0.f, 0.f, 0.f, 0.f};
        if (grp == 0) { accA = p4[i0 * LW + c]; accB = p4[i1 * LW + c]; }
        const int mx = max(cntA, cntB);
        for (int j = grp; j < mx; j += EPW) {
            if (active && j < cntA) {
                int idx = g_col[begA + j];
                float4 v = p4[idx * LW + c];
                accA.x += v.x; accA.y += v.y; accA.z += v.z; accA.w += v.w;
            }
            if (active && j < cntB) {
                int idx = g_col[begB + j];
                float4 v = p4[idx * LW + c];
                accB.x += v.x; accB.y += v.y; accB.z += v.z; accB.w += v.w;
            }
        }
        if (LW == 8) {
            #pragma unroll
            for (int off = 8; off < 32; off <<= 1) {
                accA.x += __shfl_xor_sync(0xffffffffu, accA.x, off);
                accA.y += __shfl_xor_sync(0xffffffffu, accA.y, off);
                accA.z += __shfl_xor_sync(0xffffffffu, accA.z, off);
                accA.w += __shfl_xor_sync(0xffffffffu, accA.w, off);
                accB.x += __shfl_xor_sync(0xffffffffu, accB.x, off);
                accB.y += __shfl_xor_sync(0xffffffffu, accB.y, off);
                accB.z += __shfl_xor_sync(0xffffffffu, accB.z, off);
                accB.w += __shfl_xor_sync(0xffffffffu, accB.w, off);
            }
        } else {                        // LW == 12, EPW == 2: slot1 -> slot0
            accA.x += __shfl_down_sync(0xffffffffu, accA.x, 12);
            accA.y += __shfl_down_sync(0xffffffffu, accA.y, 12);
            accA.z += __shfl_down_sync(0xffffffffu, accA.z, 12);
            accA.w += __shfl_down_sync(0xffffffffu, accA.w, 12);
            accB.x += __shfl_down_sync(0xffffffffu, accB.x, 12);
            accB.y += __shfl_down_sync(0xffffffffu, accB.y, 12);
            accB.z += __shfl_down_sync(0xffffffffu, accB.z, 12);
            accB.w += __shfl_down_sync(0xffffffffu, accB.w, 12);
        }
        if (grp == 0) {
            float dA = g_dinv[i0], dB = g_dinv[i1];
            float4 oA = {dA * accA.x, dA * accA.y, dA * accA.z, dA * accA.w};
            float4 oB = {dB * accB.x, dB * accB.y, dB * accB.z, dB * accB.w};
            o4[i0 * LW + c] = oA;
            o4[i1 * LW + c] = oB;
            if (ST) {
                s4.x += oA.x + oB.x; s4.y += oA.y + oB.y;
                s4.z += oA.z + oB.z; s4.w += oA.w + oB.w;
                q4.x += oA.x * oA.x + oB.x * oB.x;
                q4.y += oA.y * oA.y + oB.y * oB.y;
                q4.z += oA.z * oA.z + oB.z * oB.z;
                q4.w += oA.w * oA.w + oB.w * oB.w;
            }
        }
    }
    if (ST) {
        if (grp == 0) {
            atomicAdd(&bsum[c * 4 + 0], s4.x); atomicAdd(&bsq[c * 4 + 0], q4.x);
            atomicAdd(&bsum[c * 4 + 1], s4.y); atomicAdd(&bsq[c * 4 + 1], q4.y);
            atomicAdd(&bsum[c * 4 + 2], s4.z); atomicAdd(&bsq[c * 4 + 2], q4.z);
            atomicAdd(&bsum[c * 4 + 3], s4.w); atomicAdd(&bsq[c * 4 + 3], q4.w);
        }
        __syncthreads();
        float* bank = g_bnpart[LIDX][blockIdx.x & (NBANK - 1)];
        for (int i = tid; i < FPAD; i += blockDim.x) {
            atomicAdd(&bank[i],      bsum[i]);
            atomicAdd(&bank[64 + i], bsq[i]);
        }
    }
}

// ------ register-tiled GEMM, NT=4, launch-bounds reg cap for residency ------
template<int FIN, int IS, int FOUT, int NC, int NG, int NT, int LBB,
         int BNL, bool DINV_OUT, int IB, int OB>
__global__ void __launch_bounds__(NC * NG, LBB)
k_gemm(const float* __restrict__ W,
       const float* __restrict__ gv,
       const float* __restrict__ bev) {
    constexpr int NO   = 4;
    constexpr int NPB  = NG * NT;
    constexpr int SPAD = FIN + 4;
    constexpr bool BN_IN = (BNL >= 0);
    constexpr int BL = BN_IN ? BNL : 0;
    const float* __restrict__ in = buff<IB>();
    float* __restrict__ out = buff<OB>();
    __shared__ float sW[FIN * FOUT];
    __shared__ float sIn[NPB * SPAD];
    __shared__ float sbna[BN_IN ? FIN : 1];
    __shared__ float sbnc[BN_IN ? FIN : 1];
    const int tid = threadIdx.x;
    const int nthreads = NC * NG;
    for (int idx = tid; idx < FIN * FOUT / 4; idx += nthreads)
        reinterpret_cast<float4*>(sW)[idx] = reinterpret_cast<const float4*>(W)[idx];
    if (BN_IN && tid < FIN) {
        float sum = 0.f, sq = 0.f;
        #pragma unroll
        for (int b = 0; b < NBANK; b++) {
            sum += g_bnpart[BL][b][tid];
            sq  += g_bnpart[BL][b][64 + tid];
        }
        float inv_n = 1.0f / (float)N_NODES;
        float mu  = sum * inv_n;
        float var = sq * inv_n - mu * mu;
        float a = gv[tid] * rsqrtf(var + BN_EPS);
        sbna[tid] = a;
        sbnc[tid] = bev[tid] - mu * a;
    }
    const int co = tid % NC;
    const int g  = tid / NC;
    const int base = blockIdx.x * NPB;      // one tile per block
    __syncthreads();
    for (int idx = tid; idx < NPB * (FIN / 4); idx += nthreads) {
        int nl = idx / (FIN / 4), k4 = idx - nl * (FIN / 4);
        int node = base + nl;
        float4 v = {0.f, 0.f, 0.f, 0.f};
        if (node < N_NODES) {
            v = *reinterpret_cast<const float4*>(&in[node * IS + k4 * 4]);
            if (BN_IN) {
                int k = k4 * 4;
                v.x = fmaxf(fmaf(v.x, sbna[k],     sbnc[k]),     0.f);
                v.y = fmaxf(fmaf(v.y, sbna[k + 1], sbnc[k + 1]), 0.f);
                v.z = fmaxf(fmaf(v.z, sbna[k + 2], sbnc[k + 2]), 0.f);
                v.w = fmaxf(fmaf(v.w, sbna[k + 3], sbnc[k + 3]), 0.f);
            }
        }
        *reinterpret_cast<float4*>(&sIn[nl * SPAD + k4 * 4]) = v;
    }
    __syncthreads();
    float acc[NT][NO];
    #pragma unroll
    for (int j = 0; j < NT; j++)
        #pragma unroll
        for (int o = 0; o < NO; o++) acc[j][o] = 0.f;
    #pragma unroll 2
    for (int k4 = 0; k4 < FIN / 4; k4++) {
        float4 a[NT];
        #pragma unroll
        for (int j = 0; j < NT; j++)
            a[j] = *reinterpret_cast<const float4*>(
                &sIn[(g * NT + j) * SPAD + k4 * 4]);
        #pragma unroll
        for (int kk = 0; kk < 4; kk++) {
            float4 w = *reinterpret_cast<const float4*>(
                &sW[(k4 * 4 + kk) * FOUT + co * NO]);
            #pragma unroll
            for (int j = 0; j < NT; j++) {
                float av = (kk == 0) ? a[j].x : (kk == 1) ? a[j].y
                         : (kk == 2) ? a[j].z : a[j].w;
                acc[j][0] = fmaf(av, w.x, acc[j][0]);
                acc[j][1] = fmaf(av, w.y, acc[j][1]);
                acc[j][2] = fmaf(av, w.z, acc[j][2]);
                acc[j][3] = fmaf(av, w.w, acc[j][3]);
            }
        }
    }
    #pragma unroll
    for (int j = 0; j < NT; j++) {
        int node = base + g * NT + j;
        if (node < N_NODES) {
            float d = DINV_OUT ? g_dinv[node] : 1.f;
            float4 o = {acc[j][0] * d, acc[j][1] * d, acc[j][2] * d, acc[j][3] * d};
            *reinterpret_cast<float4*>(&out[node * FOUT + co * NO]) = o;
        }
    }
}

// ------- final apply: out = bn3(b2 rows, stride 32), params inline ----------
__global__ void k_apply(const float* __restrict__ gv,
                        const float* __restrict__ bev,
                        float* __restrict__ out) {
    __shared__ float sa[32];
    __shared__ float sc[32];
    const int tid = threadIdx.x;
    if (tid < 32) {
        float sum = 0.f, sq = 0.f;
        #pragma unroll
        for (int b = 0; b < NBANK; b++) {
            sum += g_bnpart[2][b][tid];
            sq  += g_bnpart[2][b][64 + tid];
        }
        float inv_n = 1.0f / (float)N_NODES;
        float mu  = sum * inv_n;
        float var = sq * inv_n - mu * mu;
        float a = gv[tid] * rsqrtf(var + BN_EPS);
        sa[tid] = a;
        sc[tid] = bev[tid] - mu * a;
    }
    __syncthreads();
    const int total = N_NODES * 32;
    const int stride = gridDim.x * blockDim.x;
    for (int idx = blockIdx.x * blockDim.x + tid; idx < total; idx += stride) {
        int f = idx & 31;
        out[idx] = fmaf(((const float*)g_b2)[idx], sa[f], sc[f]);
    }
}

// ---------------- launcher ----------------
extern "C" void kernel_launch(void* const* d_in, const int* in_sizes, int n_in,
                              void* d_out, int out_size) {
    const float* x   = (const float*)d_in[0];
    const int*   ei  = (const int*)d_in[1];          // int32
    const float* W1  = (const float*)d_in[2];
    const float* g1  = (const float*)d_in[4];
    const float* be1 = (const float*)d_in[5];
    const float* W2  = (const float*)d_in[6];
    const float* g2  = (const float*)d_in[8];
    const float* be2 = (const float*)d_in[9];
    const float* W3  = (const float*)d_in[10];
    const float* g3  = (const float*)d_in[12];
    const float* be3 = (const float*)d_in[13];
    float* out = (float*)d_out;

    // zero per-call state (memset nodes, not kernel launches)
    void* pa;
    cudaGetSymbolAddress(&pa, g_count);
    cudaMemsetAsync(pa, 0, sizeof(int) * N_NODES);
    cudaGetSymbolAddress(&pa, g_bnpart);
    cudaMemsetAsync(pa, 0, sizeof(float) * 3 * NBANK * 128);

    // ---- build + prep ----
    k_scatter<<<(N_EDGES / 2 + 255) / 256, 256>>>(ei);        // 0
    k_prep<<<(N_NODES + 255) / 256, 256>>>(x);                // 1

    // ---- layer 1 fused: gather(20f) + GEMM 20->64 + BN1 stats ----
    k_layer1<<<2048, 256>>>(W1);                              // 2: b0 -> b2

    // ---- layer 2 ----  NT=4, NPB=80, LBB=5 (53-reg cap, 5 resident)
    k_gemm<64, 64, 48, 12, 20, 4, 5, 0, true, 2, 0>
        <<<(N_NODES + 79) / 80, 240>>>(W2, g1, be1);          // 3 <- PROFILED: b2 -> b0
    k_gather<48, 2, 0, 1, 1><<<2048, 256>>>();                // 4: b0 -> b1 (+BN2 stats)

    // ---- layer 3 ----  NT=4, NPB=128, LBB=5 (50-reg cap, 5 resident)
    k_gemm<48, 48, 32, 8, 32, 4, 5, 1, true, 1, 0>
        <<<(N_NODES + 127) / 128, 256>>>(W3, g2, be2);        // 5: b1 -> b0
    k_gather<32, 4, 0, 2, 2><<<2048, 256>>>();                // 6: b0 -> b2 (+BN3 stats)

    // ---- final BN apply (params inline) ----
    k_apply<<<2048, 256>>>(g3, be3, out);                     // 7
}